// round 8
// baseline (speedup 1.0000x reference)
#include <cuda_runtime.h>
#include <cuda_bf16.h>
#include <cstdint>

#define B_   16
#define C_   64
#define H_   64
#define W_   64
#define N_   4096
#define M_   1024
#define D8   8
#define D2   32
#define CH48 48

// Device scratch (no cudaMalloc allowed)
__device__ float d_tmp[B_ * CH48 * N_];   // only theta (ch 0..7) used
__device__ float d_phi[B_ * D8 * M_];     // pooled phi (f32)
__device__ float d_g[B_ * D2 * M_];       // pooled g   (f32)

// ---- f32x2 packed helpers ---------------------------------------------------
__device__ __forceinline__ void ffma2(unsigned long long& d,
                                      unsigned long long a,
                                      unsigned long long b) {
    asm("fma.rn.f32x2 %0, %1, %2, %0;" : "+l"(d) : "l"(a), "l"(b));
}
__device__ __forceinline__ unsigned long long pack_ff(float lo, float hi) {
    unsigned long long r;
    asm("mov.b64 %0, {%1,%2};" : "=l"(r) : "f"(lo), "f"(hi));
    return r;
}
__device__ __forceinline__ void unpack_ff(unsigned long long v, float& lo, float& hi) {
    asm("mov.b64 {%0,%1}, %2;" : "=f"(lo), "=f"(hi) : "l"(v));
}

// ---- mma wrappers (baseline PTX, legal on plain sm_103) ----------------------
__device__ __forceinline__ void mma1688_tf32(float& d0, float& d1, float& d2, float& d3,
                                             uint32_t a0, uint32_t a1, uint32_t a2, uint32_t a3,
                                             uint32_t b0, uint32_t b1) {
    asm volatile(
        "mma.sync.aligned.m16n8k8.row.col.f32.tf32.tf32.f32 "
        "{%0,%1,%2,%3}, {%4,%5,%6,%7}, {%8,%9}, {%0,%1,%2,%3};"
        : "+f"(d0), "+f"(d1), "+f"(d2), "+f"(d3)
        : "r"(a0), "r"(a1), "r"(a2), "r"(a3), "r"(b0), "r"(b1));
}
__device__ __forceinline__ void mma_fp8(float& d0, float& d1, float& d2, float& d3,
                                        uint32_t a0, uint32_t a1, uint32_t a2, uint32_t a3,
                                        uint32_t b0, uint32_t b1) {
    asm volatile(
        "mma.sync.aligned.m16n8k32.row.col.f32.e4m3.e4m3.f32 "
        "{%0,%1,%2,%3}, {%4,%5,%6,%7}, {%8,%9}, {%0,%1,%2,%3};"
        : "+f"(d0), "+f"(d1), "+f"(d2), "+f"(d3)
        : "r"(a0), "r"(a1), "r"(a2), "r"(a3), "r"(b0), "r"(b1));
}
__device__ __forceinline__ uint32_t to_tf32(float v) {
    uint32_t r;
    asm("cvt.rna.tf32.f32 %0, %1;" : "=r"(r) : "f"(v));
    return r;
}
__device__ __forceinline__ uint16_t e4m3x2_of(float lo, float hi) {
    uint16_t r;   // PTX: cvt d, a, b -> d.hi = cvt(a), d.lo = cvt(b)
    asm("cvt.rn.satfinite.e4m3x2.f32 %0, %1, %2;" : "=h"(r) : "f"(hi), "f"(lo));
    return r;
}
__device__ __forceinline__ float ex2f(float v) {
    float r;
    asm("ex2.approx.f32 %0, %1;" : "=f"(r) : "f"(v));
    return r;
}

// ---------------------------------------------------------------------------
// P1: FUSED conv1x1 + 2x2 maxpool (proven in R7)
// ---------------------------------------------------------------------------
__global__ void __launch_bounds__(256) convpool_kernel(
    const float* __restrict__ x,
    const float* __restrict__ w_theta, const float* __restrict__ b_theta,
    const float* __restrict__ w_phi,   const float* __restrict__ b_phi,
    const float* __restrict__ w_g,     const float* __restrict__ b_g)
{
    __shared__ float w_s[C_ * 24];
    __shared__ float bias_s[24];
    int tid    = threadIdx.x;
    int chbase = blockIdx.y * 24;

    for (int i = tid; i < C_ * 24; i += 256) {
        int c = i / 24, chp = i % 24;
        int ch = chbase + chp;
        float v;
        if (ch < 8)       v = w_theta[ch * C_ + c];
        else if (ch < 16) v = w_phi[(ch - 8) * C_ + c];
        else              v = w_g[(ch - 16) * C_ + c];
        w_s[i] = v;
    }
    if (tid < 24) {
        int ch = chbase + tid;
        bias_s[tid] = (ch < 8) ? b_theta[ch]
                    : (ch < 16 ? b_phi[ch - 8] : b_g[ch - 16]);
    }
    __syncthreads();

    int idx = blockIdx.x * 256 + tid;
    int b  = idx >> 10;
    int q  = idx & 1023;
    int mh = q >> 5, mw = q & 31;
    int n00 = (2 * mh) * W_ + 2 * mw;

    unsigned long long accR0[24], accR1[24];
    #pragma unroll
    for (int j = 0; j < 24; j++) {
        unsigned long long bb = pack_ff(bias_s[j], bias_s[j]);
        accR0[j] = bb; accR1[j] = bb;
    }

    const float* xb = x + ((size_t)b * C_) * N_ + n00;
    #pragma unroll 4
    for (int c = 0; c < C_; c++) {
        unsigned long long x0 = *(const unsigned long long*)(xb + (size_t)c * N_);
        unsigned long long x1 = *(const unsigned long long*)(xb + (size_t)c * N_ + W_);
        const float* wrow = w_s + c * 24;
        #pragma unroll
        for (int j = 0; j < 24; j++) {
            float wj = wrow[j];
            unsigned long long w2 = pack_ff(wj, wj);
            ffma2(accR0[j], x0, w2);
            ffma2(accR1[j], x1, w2);
        }
    }

    int m = mh * 32 + mw;
    if (chbase == 0) {
        float* tb = d_tmp + (size_t)b * CH48 * N_ + n00;
        #pragma unroll
        for (int ch = 0; ch < 8; ch++) {
            *(unsigned long long*)(tb + (size_t)ch * N_)      = accR0[ch];
            *(unsigned long long*)(tb + (size_t)ch * N_ + W_) = accR1[ch];
        }
        #pragma unroll
        for (int ch = 8; ch < 16; ch++) {
            float a0, a1, b0, b1;
            unpack_ff(accR0[ch], a0, a1);
            unpack_ff(accR1[ch], b0, b1);
            d_phi[((size_t)b * D8 + (ch - 8)) * M_ + m]
                = fmaxf(fmaxf(a0, a1), fmaxf(b0, b1));
        }
        #pragma unroll
        for (int ch = 16; ch < 24; ch++) {
            float a0, a1, b0, b1;
            unpack_ff(accR0[ch], a0, a1);
            unpack_ff(accR1[ch], b0, b1);
            d_g[((size_t)b * D2 + (ch - 16)) * M_ + m]
                = fmaxf(fmaxf(a0, a1), fmaxf(b0, b1));
        }
    } else {
        #pragma unroll
        for (int chp = 0; chp < 24; chp++) {
            float a0, a1, b0, b1;
            unpack_ff(accR0[chp], a0, a1);
            unpack_ff(accR1[chp], b0, b1);
            d_g[((size_t)b * D2 + 8 + chp) * M_ + m]
                = fmaxf(fmaxf(a0, a1), fmaxf(b0, b1));
        }
    }
}

// ---------------------------------------------------------------------------
// Main kernel v4: tf32 logits mma -> ex2 in regs -> e4m3 P via warp-private
// smem scratch -> m16n8k32 fp8 PV mma (half the PV mma count of bf16).
// g stored e4m3 [c][m], row stride 1040 B -> B-frag lanes on 32 distinct banks.
// P8 scratch rows stride 48 B -> STS/LDS conflict-free.
// AG/XCH alias the dead g/phi region after the main loop.
// ---------------------------------------------------------------------------
#define GS8    1040                         // g row stride (bytes)
#define PHISTR 1032                         // phi row stride (f32 words)
#define P8STR  48                           // P8 row stride (bytes)
#define XSTR   33
#define OFF_G8   0                          // 32*1040 = 33280
#define OFF_PHI  33280                      // 33024 -> 66304
#define OFF_TH   66304                      // 4096  -> 70400
#define OFF_WO   70400                      // 8192  -> 78592
#define OFF_BO   78592                      // 256   -> 78848
#define OFF_RS   78848                      // 1024  -> 79872
#define OFF_P8   79872                      // 16*768 = 12288 -> 92160
#define OFF_AG   0                          // alias G8 (dead after loop)
#define OFF_XCH  18432                      // alias G8/PHI (dead after loop)
#define SMEM_REQ 92160

__global__ void __launch_bounds__(512, 1) attn_main_kernel(
    const float* __restrict__ x,
    const float* __restrict__ w_o,
    const float* __restrict__ b_o,
    const float* __restrict__ sigma,
    float* __restrict__ out)
{
    extern __shared__ char smp[];
    uint32_t* phi_s = (uint32_t*)(smp + OFF_PHI);
    uint32_t* th_s  = (uint32_t*)(smp + OFF_TH);
    float*    wo_s  = (float*)(smp + OFF_WO);
    float*    bo_s  = (float*)(smp + OFF_BO);
    float*    rs_s  = (float*)(smp + OFF_RS);
    float*    ag_s  = (float*)(smp + OFF_AG);

    int tid   = threadIdx.x;
    int warp  = tid >> 5, lane = tid & 31;
    int b     = blockIdx.y;
    int qbase = blockIdx.x * 128;

    // ---- cooperative loads ----
    {
        const float* psrc = d_phi + (size_t)b * D8 * M_;
        for (int i = tid; i < D8 * M_; i += 512) {
            int d = i >> 10, m = i & 1023;
            phi_s[d * PHISTR + m] = to_tf32(psrc[i]);
        }
        const float* gsrc = d_g + (size_t)b * D2 * M_;
        for (int i = tid; i < D2 * (M_ / 2); i += 512) {
            int c = i >> 9;
            int m = (i & 511) * 2;
            float2 gv = *(const float2*)(gsrc + (size_t)c * M_ + m);
            *(uint16_t*)(smp + OFF_G8 + c * GS8 + m) = e4m3x2_of(gv.x, gv.y);
        }
        const float* tsrc = d_tmp + (size_t)b * CH48 * N_ + qbase;
        for (int i = tid; i < 1024; i += 512) {
            int d = i >> 7, q = i & 127;
            th_s[q * 8 + d] = to_tf32(tsrc[(size_t)d * N_ + q] * 1.4426950408889634f);
        }
        const float4* w4 = (const float4*)w_o;
        float4* ws4 = (float4*)wo_s;
        for (int i = tid; i < 64 * 32 / 4; i += 512) ws4[i] = w4[i];
        if (tid < 64) bo_s[tid] = b_o[tid];
    }
    __syncthreads();

    int pair = warp >> 1;
    int half = warp & 1;
    int q0   = pair * 16;
    int g    = lane >> 2;
    int tg   = lane & 3;

    uint32_t ta0 = th_s[(q0 + g) * 8 + tg];
    uint32_t ta1 = th_s[(q0 + g + 8) * 8 + tg];
    uint32_t ta2 = th_s[(q0 + g) * 8 + tg + 4];
    uint32_t ta3 = th_s[(q0 + g + 8) * 8 + tg + 4];

    float rs_lo = 0.f, rs_hi = 0.f;
    float acc[4][4];
    #pragma unroll
    for (int nt = 0; nt < 4; nt++)
        #pragma unroll
        for (int r = 0; r < 4; r++) acc[nt][r] = 0.f;

    const uint32_t* phiB0 = phi_s + tg * PHISTR + g + half * 512;
    const uint32_t* phiB1 = phi_s + (tg + 4) * PHISTR + g + half * 512;
    const char*     gB8   = smp + OFF_G8 + g * GS8 + half * 512 + 4 * tg;

    char* p8w   = smp + OFF_P8 + warp * (16 * P8STR);
    char* p8_g  = p8w + g * P8STR;            // this thread's row g
    char* p8_g8 = p8w + (g + 8) * P8STR;      // row g+8

    // ---- 16 windows of 32 keys ----
    #pragma unroll 2
    for (int u = 0; u < 16; u++) {
        int mo = u * 32;

        // logits: 4 tf32 mmas over 8-key subgroups
        float e[4][4];
        #pragma unroll
        for (int s = 0; s < 4; s++) {
            e[s][0] = e[s][1] = e[s][2] = e[s][3] = 0.f;
            mma1688_tf32(e[s][0], e[s][1], e[s][2], e[s][3],
                         ta0, ta1, ta2, ta3,
                         phiB0[mo + 8 * s], phiB1[mo + 8 * s]);
        }
        // exp + rowsums + e4m3 pack to warp-private scratch
        #pragma unroll
        for (int s = 0; s < 4; s++) {
            e[s][0] = ex2f(e[s][0]); e[s][1] = ex2f(e[s][1]);
            e[s][2] = ex2f(e[s][2]); e[s][3] = ex2f(e[s][3]);
            rs_lo += e[s][0] + e[s][1];
            rs_hi += e[s][2] + e[s][3];
            *(uint16_t*)(p8_g  + s * 8 + 2 * tg) = e4m3x2_of(e[s][0], e[s][1]);
            *(uint16_t*)(p8_g8 + s * 8 + 2 * tg) = e4m3x2_of(e[s][2], e[s][3]);
        }
        __syncwarp();
        uint32_t a0 = *(const uint32_t*)(p8_g  + 4 * tg);
        uint32_t a1 = *(const uint32_t*)(p8_g8 + 4 * tg);
        uint32_t a2 = *(const uint32_t*)(p8_g  + 16 + 4 * tg);
        uint32_t a3 = *(const uint32_t*)(p8_g8 + 16 + 4 * tg);
        __syncwarp();

        // PV: 4 fp8 k32 mmas (32 keys x 32 channels)
        #pragma unroll
        for (int nt = 0; nt < 4; nt++) {
            uint32_t b0 = *(const uint32_t*)(gB8 + nt * (8 * GS8) + mo);
            uint32_t b1 = *(const uint32_t*)(gB8 + nt * (8 * GS8) + mo + 16);
            mma_fp8(acc[nt][0], acc[nt][1], acc[nt][2], acc[nt][3],
                    a0, a1, a2, a3, b0, b1);
        }
    }

    // ---- rowsums over quad ----
    rs_lo += __shfl_xor_sync(0xffffffffu, rs_lo, 1);
    rs_lo += __shfl_xor_sync(0xffffffffu, rs_lo, 2);
    rs_hi += __shfl_xor_sync(0xffffffffu, rs_hi, 1);
    rs_hi += __shfl_xor_sync(0xffffffffu, rs_hi, 2);
    if (tg == 0) {
        rs_s[warp * 16 + g]     = rs_lo;
        rs_s[warp * 16 + 8 + g] = rs_hi;
    }
    __syncthreads();   // all g/phi reads done -> AG/XCH aliases now safe

    // ---- pair combine ----
    float* xch = (float*)(smp + OFF_XCH) + pair * (16 * XSTR);
    if (half == 1) {
        #pragma unroll
        for (int nt = 0; nt < 4; nt++) {
            int c0 = nt * 8 + 2 * tg;
            xch[g * XSTR + c0]           = acc[nt][0];
            xch[g * XSTR + c0 + 1]       = acc[nt][1];
            xch[(g + 8) * XSTR + c0]     = acc[nt][2];
            xch[(g + 8) * XSTR + c0 + 1] = acc[nt][3];
        }
    }
    __syncthreads();
    if (half == 0) {
        float inv_lo = 1.f / (rs_s[(2 * pair) * 16 + g]     + rs_s[(2 * pair + 1) * 16 + g]);
        float inv_hi = 1.f / (rs_s[(2 * pair) * 16 + g + 8] + rs_s[(2 * pair + 1) * 16 + g + 8]);
        #pragma unroll
        for (int nt = 0; nt < 4; nt++) {
            int c0 = nt * 8 + 2 * tg;
            ag_s[(q0 + g) * 36 + c0]         = (acc[nt][0] + xch[g * XSTR + c0])           * inv_lo;
            ag_s[(q0 + g) * 36 + c0 + 1]     = (acc[nt][1] + xch[g * XSTR + c0 + 1])       * inv_lo;
            ag_s[(q0 + g + 8) * 36 + c0]     = (acc[nt][2] + xch[(g + 8) * XSTR + c0])     * inv_hi;
            ag_s[(q0 + g + 8) * 36 + c0 + 1] = (acc[nt][3] + xch[(g + 8) * XSTR + c0 + 1]) * inv_hi;
        }
    }
    __syncthreads();

    // ---- projection + residual epilogue ----
    float sig = sigma[0];
    int nl = tid & 127;
    int kh = tid >> 7;

    float ag[32];
    #pragma unroll
    for (int c4 = 0; c4 < 8; c4++) {
        float4 v = *(const float4*)(ag_s + nl * 36 + 4 * c4);
        ag[4 * c4 + 0] = v.x; ag[4 * c4 + 1] = v.y;
        ag[4 * c4 + 2] = v.z; ag[4 * c4 + 3] = v.w;
    }
    size_t xoff_base = ((size_t)b * C_ + kh * 16) * N_ + qbase + nl;
    #pragma unroll 4
    for (int kk = 0; kk < 16; kk++) {
        int k = kh * 16 + kk;
        float val = bo_s[k];
        const float4* wrow = (const float4*)(wo_s + k * 32);
        #pragma unroll
        for (int c4 = 0; c4 < 8; c4++) {
            float4 w4 = wrow[c4];
            val += w4.x * ag[4 * c4] + w4.y * ag[4 * c4 + 1]
                 + w4.z * ag[4 * c4 + 2] + w4.w * ag[4 * c4 + 3];
        }
        size_t off = xoff_base + (size_t)kk * N_;
        out[off] = x[off] + sig * val;
    }
}

// ---------------------------------------------------------------------------
extern "C" void kernel_launch(void* const* d_in, const int* in_sizes, int n_in,
                              void* d_out, int out_size)
{
    const float* x       = (const float*)d_in[0];
    const float* w_theta = (const float*)d_in[1];
    const float* b_theta = (const float*)d_in[2];
    const float* w_phi   = (const float*)d_in[3];
    const float* b_phi   = (const float*)d_in[4];
    const float* w_g     = (const float*)d_in[5];
    const float* b_g     = (const float*)d_in[6];
    const float* w_o     = (const float*)d_in[7];
    const float* b_o     = (const float*)d_in[8];
    const float* sigma   = (const float*)d_in[9];
    float* out = (float*)d_out;

    convpool_kernel<<<dim3(B_ * 1024 / 256, 2), 256>>>(x, w_theta, b_theta,
                                                       w_phi, b_phi, w_g, b_g);

    cudaFuncSetAttribute(attn_main_kernel,
                         cudaFuncAttributeMaxDynamicSharedMemorySize, SMEM_REQ);
    attn_main_kernel<<<dim3(N_ / 128, B_), 512, SMEM_REQ>>>(x, w_o, b_o, sigma, out);
}

// round 9
// speedup vs baseline: 2.0024x; 2.0024x over previous
#include <cuda_runtime.h>
#include <cuda_bf16.h>
#include <cstdint>

#define B_   16
#define C_   64
#define H_   64
#define W_   64
#define N_   4096
#define M_   1024
#define D8   8
#define D2   32
#define CH48 48

// Device scratch (no cudaMalloc allowed)
__device__ float d_tmp[B_ * CH48 * N_];   // only theta (ch 0..7) used
__device__ float d_phi[B_ * D8 * M_];     // pooled phi (f32)
__device__ float d_g[B_ * D2 * M_];       // pooled g   (f32)

// ---- f32x2 packed helpers ---------------------------------------------------
__device__ __forceinline__ void ffma2(unsigned long long& d,
                                      unsigned long long a,
                                      unsigned long long b) {
    asm("fma.rn.f32x2 %0, %1, %2, %0;" : "+l"(d) : "l"(a), "l"(b));
}
__device__ __forceinline__ unsigned long long pack_ff(float lo, float hi) {
    unsigned long long r;
    asm("mov.b64 %0, {%1,%2};" : "=l"(r) : "f"(lo), "f"(hi));
    return r;
}
__device__ __forceinline__ void unpack_ff(unsigned long long v, float& lo, float& hi) {
    asm("mov.b64 {%0,%1}, %2;" : "=f"(lo), "=f"(hi) : "l"(v));
}

// ---- mma wrappers (baseline PTX, legal on plain sm_103) ----------------------
__device__ __forceinline__ void mma16816(float& d0, float& d1, float& d2, float& d3,
                                         uint32_t a0, uint32_t a1, uint32_t a2, uint32_t a3,
                                         uint32_t b0, uint32_t b1) {
    asm volatile(
        "mma.sync.aligned.m16n8k16.row.col.f32.bf16.bf16.f32 "
        "{%0,%1,%2,%3}, {%4,%5,%6,%7}, {%8,%9}, {%0,%1,%2,%3};"
        : "+f"(d0), "+f"(d1), "+f"(d2), "+f"(d3)
        : "r"(a0), "r"(a1), "r"(a2), "r"(a3), "r"(b0), "r"(b1));
}
__device__ __forceinline__ void mma1688_tf32(float& d0, float& d1, float& d2, float& d3,
                                             uint32_t a0, uint32_t a1, uint32_t a2, uint32_t a3,
                                             uint32_t b0, uint32_t b1) {
    asm volatile(
        "mma.sync.aligned.m16n8k8.row.col.f32.tf32.tf32.f32 "
        "{%0,%1,%2,%3}, {%4,%5,%6,%7}, {%8,%9}, {%0,%1,%2,%3};"
        : "+f"(d0), "+f"(d1), "+f"(d2), "+f"(d3)
        : "r"(a0), "r"(a1), "r"(a2), "r"(a3), "r"(b0), "r"(b1));
}
__device__ __forceinline__ uint32_t to_tf32(float v) {
    uint32_t r;
    asm("cvt.rna.tf32.f32 %0, %1;" : "=r"(r) : "f"(v));
    return r;
}
__device__ __forceinline__ uint32_t bf16x2_of(float lo, float hi) {
    uint32_t r;
    asm("cvt.rn.bf16x2.f32 %0, %1, %2;" : "=r"(r) : "f"(hi), "f"(lo));
    return r;
}
__device__ __forceinline__ float ex2f(float v) {
    float r;
    asm("ex2.approx.f32 %0, %1;" : "=f"(r) : "f"(v));
    return r;
}

// ---------------------------------------------------------------------------
// P1: FUSED conv1x1 + 2x2 maxpool (proven)
// ---------------------------------------------------------------------------
__global__ void __launch_bounds__(256) convpool_kernel(
    const float* __restrict__ x,
    const float* __restrict__ w_theta, const float* __restrict__ b_theta,
    const float* __restrict__ w_phi,   const float* __restrict__ b_phi,
    const float* __restrict__ w_g,     const float* __restrict__ b_g)
{
    __shared__ float w_s[C_ * 24];
    __shared__ float bias_s[24];
    int tid    = threadIdx.x;
    int chbase = blockIdx.y * 24;

    for (int i = tid; i < C_ * 24; i += 256) {
        int c = i / 24, chp = i % 24;
        int ch = chbase + chp;
        float v;
        if (ch < 8)       v = w_theta[ch * C_ + c];
        else if (ch < 16) v = w_phi[(ch - 8) * C_ + c];
        else              v = w_g[(ch - 16) * C_ + c];
        w_s[i] = v;
    }
    if (tid < 24) {
        int ch = chbase + tid;
        bias_s[tid] = (ch < 8) ? b_theta[ch]
                    : (ch < 16 ? b_phi[ch - 8] : b_g[ch - 16]);
    }
    __syncthreads();

    int idx = blockIdx.x * 256 + tid;
    int b  = idx >> 10;
    int q  = idx & 1023;
    int mh = q >> 5, mw = q & 31;
    int n00 = (2 * mh) * W_ + 2 * mw;

    unsigned long long accR0[24], accR1[24];
    #pragma unroll
    for (int j = 0; j < 24; j++) {
        unsigned long long bb = pack_ff(bias_s[j], bias_s[j]);
        accR0[j] = bb; accR1[j] = bb;
    }

    const float* xb = x + ((size_t)b * C_) * N_ + n00;
    #pragma unroll 4
    for (int c = 0; c < C_; c++) {
        unsigned long long x0 = *(const unsigned long long*)(xb + (size_t)c * N_);
        unsigned long long x1 = *(const unsigned long long*)(xb + (size_t)c * N_ + W_);
        const float* wrow = w_s + c * 24;
        #pragma unroll
        for (int j = 0; j < 24; j++) {
            float wj = wrow[j];
            unsigned long long w2 = pack_ff(wj, wj);
            ffma2(accR0[j], x0, w2);
            ffma2(accR1[j], x1, w2);
        }
    }

    int m = mh * 32 + mw;
    if (chbase == 0) {
        float* tb = d_tmp + (size_t)b * CH48 * N_ + n00;
        #pragma unroll
        for (int ch = 0; ch < 8; ch++) {
            *(unsigned long long*)(tb + (size_t)ch * N_)      = accR0[ch];
            *(unsigned long long*)(tb + (size_t)ch * N_ + W_) = accR1[ch];
        }
        #pragma unroll
        for (int ch = 8; ch < 16; ch++) {
            float a0, a1, b0, b1;
            unpack_ff(accR0[ch], a0, a1);
            unpack_ff(accR1[ch], b0, b1);
            d_phi[((size_t)b * D8 + (ch - 8)) * M_ + m]
                = fmaxf(fmaxf(a0, a1), fmaxf(b0, b1));
        }
        #pragma unroll
        for (int ch = 16; ch < 24; ch++) {
            float a0, a1, b0, b1;
            unpack_ff(accR0[ch], a0, a1);
            unpack_ff(accR1[ch], b0, b1);
            d_g[((size_t)b * D2 + (ch - 16)) * M_ + m]
                = fmaxf(fmaxf(a0, a1), fmaxf(b0, b1));
        }
    } else {
        #pragma unroll
        for (int chp = 0; chp < 24; chp++) {
            float a0, a1, b0, b1;
            unpack_ff(accR0[chp], a0, a1);
            unpack_ff(accR1[chp], b0, b1);
            d_g[((size_t)b * D2 + 8 + chp) * M_ + m]
                = fmaxf(fmaxf(a0, a1), fmaxf(b0, b1));
        }
    }
}

// ---------------------------------------------------------------------------
// Main kernel (R7 structure, occupancy-tuned):
//   logits : m16n8k8 tf32 mma (theta prescaled by log2e)
//   softmax: ex2.approx on C fragments (exact math, bounded logits)
//   PV     : bf16x2 frags -> m16n8k16 bf16 mma. No P smem.
// __launch_bounds__(512, 2): cap regs at 64 -> 2 CTAs/SM (32 warps).
// unroll 1 on the key loop: TLP replaces ILP for latency hiding.
// AG/XCH alias the dead G region after the main loop -> smem 112640 B,
// so two CTAs fit in the 228KB smem budget.
// ---------------------------------------------------------------------------
#define PHISTR 1032
#define GSTR2  2064
#define XSTR   33
#define OFF_G    0                          // 66048
#define OFF_PHI  66048                      // 33024 -> 99072
#define OFF_TH   99072                      // 4096  -> 103168
#define OFF_WO   103168                     // 8192  -> 111360
#define OFF_BO   111360                     // 256   -> 111616
#define OFF_RS   111616                     // 1024  -> 112640
#define OFF_AG   0                          // alias G (dead after loop), 18432
#define OFF_XCH  18432                      // alias G, 16896 -> 35328 < 66048
#define SMEM_REQ 112640

__global__ void __launch_bounds__(512, 2) attn_main_kernel(
    const float* __restrict__ x,
    const float* __restrict__ w_o,
    const float* __restrict__ b_o,
    const float* __restrict__ sigma,
    float* __restrict__ out)
{
    extern __shared__ char smp[];
    uint32_t* phi_s = (uint32_t*)(smp + OFF_PHI);
    uint32_t* th_s  = (uint32_t*)(smp + OFF_TH);
    float*    wo_s  = (float*)(smp + OFF_WO);
    float*    bo_s  = (float*)(smp + OFF_BO);
    float*    rs_s  = (float*)(smp + OFF_RS);
    float*    ag_s  = (float*)(smp + OFF_AG);

    int tid   = threadIdx.x;
    int warp  = tid >> 5, lane = tid & 31;
    int b     = blockIdx.y;
    int qbase = blockIdx.x * 128;

    // ---- cooperative loads ----
    {
        const float* psrc = d_phi + (size_t)b * D8 * M_;
        for (int i = tid; i < D8 * M_; i += 512) {
            int d = i >> 10, m = i & 1023;
            phi_s[d * PHISTR + m] = to_tf32(psrc[i]);
        }
        const float* gsrc = d_g + (size_t)b * D2 * M_;
        for (int i = tid; i < D2 * (M_ / 2); i += 512) {
            int c = i >> 9;
            int m = (i & 511) * 2;
            float2 gv = *(const float2*)(gsrc + (size_t)c * M_ + m);
            __nv_bfloat162 h = __floats2bfloat162_rn(gv.x, gv.y);
            *(uint32_t*)(smp + OFF_G + c * GSTR2 + m * 2) = *(uint32_t*)&h;
        }
        const float* tsrc = d_tmp + (size_t)b * CH48 * N_ + qbase;
        for (int i = tid; i < 1024; i += 512) {
            int d = i >> 7, q = i & 127;
            th_s[q * 8 + d] = to_tf32(tsrc[(size_t)d * N_ + q] * 1.4426950408889634f);
        }
        const float4* w4 = (const float4*)w_o;
        float4* ws4 = (float4*)wo_s;
        for (int i = tid; i < 64 * 32 / 4; i += 512) ws4[i] = w4[i];
        if (tid < 64) bo_s[tid] = b_o[tid];
    }
    __syncthreads();

    int pair = warp >> 1;
    int half = warp & 1;
    int q0   = pair * 16;
    int g    = lane >> 2;
    int tg   = lane & 3;

    uint32_t ta0 = th_s[(q0 + g) * 8 + tg];
    uint32_t ta1 = th_s[(q0 + g + 8) * 8 + tg];
    uint32_t ta2 = th_s[(q0 + g) * 8 + tg + 4];
    uint32_t ta3 = th_s[(q0 + g + 8) * 8 + tg + 4];

    float rs_lo = 0.f, rs_hi = 0.f;
    float acc[4][4];
    #pragma unroll
    for (int nt = 0; nt < 4; nt++)
        #pragma unroll
        for (int r = 0; r < 4; r++) acc[nt][r] = 0.f;

    const uint32_t* phiB0 = phi_s + tg * PHISTR + g + half * 512;
    const uint32_t* phiB1 = phi_s + (tg + 4) * PHISTR + g + half * 512;
    const char*     gB    = smp + OFF_G + g * GSTR2 + (half * 512 + 2 * tg) * 2;

    // ---- 32 units of 16 keys (unroll 1: minimize live registers) ----
    #pragma unroll 1
    for (int u = 0; u < 32; u++) {
        int mo = u * 16;
        float e0 = 0.f, e1 = 0.f, e2 = 0.f, e3 = 0.f;
        mma1688_tf32(e0, e1, e2, e3, ta0, ta1, ta2, ta3, phiB0[mo], phiB1[mo]);
        float f0 = 0.f, f1 = 0.f, f2 = 0.f, f3 = 0.f;
        mma1688_tf32(f0, f1, f2, f3, ta0, ta1, ta2, ta3, phiB0[mo + 8], phiB1[mo + 8]);

        e0 = ex2f(e0); e1 = ex2f(e1); e2 = ex2f(e2); e3 = ex2f(e3);
        f0 = ex2f(f0); f1 = ex2f(f1); f2 = ex2f(f2); f3 = ex2f(f3);
        rs_lo += (e0 + e1) + (f0 + f1);
        rs_hi += (e2 + e3) + (f2 + f3);

        uint32_t a0 = bf16x2_of(e0, e1);
        uint32_t a1 = bf16x2_of(e2, e3);
        uint32_t a2 = bf16x2_of(f0, f1);
        uint32_t a3 = bf16x2_of(f2, f3);

        #pragma unroll
        for (int nt = 0; nt < 4; nt++) {
            uint32_t b0 = *(const uint32_t*)(gB + nt * (8 * GSTR2) + mo * 2);
            uint32_t b1 = *(const uint32_t*)(gB + nt * (8 * GSTR2) + (mo + 8) * 2);
            mma16816(acc[nt][0], acc[nt][1], acc[nt][2], acc[nt][3],
                     a0, a1, a2, a3, b0, b1);
        }
    }

    // ---- rowsums over quad ----
    rs_lo += __shfl_xor_sync(0xffffffffu, rs_lo, 1);
    rs_lo += __shfl_xor_sync(0xffffffffu, rs_lo, 2);
    rs_hi += __shfl_xor_sync(0xffffffffu, rs_hi, 1);
    rs_hi += __shfl_xor_sync(0xffffffffu, rs_hi, 2);
    if (tg == 0) {
        rs_s[warp * 16 + g]     = rs_lo;
        rs_s[warp * 16 + 8 + g] = rs_hi;
    }
    __syncthreads();   // all G/phi reads done -> AG/XCH aliases now safe

    // ---- pair combine ----
    float* xch = (float*)(smp + OFF_XCH) + pair * (16 * XSTR);
    if (half == 1) {
        #pragma unroll
        for (int nt = 0; nt < 4; nt++) {
            int c0 = nt * 8 + 2 * tg;
            xch[g * XSTR + c0]           = acc[nt][0];
            xch[g * XSTR + c0 + 1]       = acc[nt][1];
            xch[(g + 8) * XSTR + c0]     = acc[nt][2];
            xch[(g + 8) * XSTR + c0 + 1] = acc[nt][3];
        }
    }
    __syncthreads();
    if (half == 0) {
        float inv_lo = 1.f / (rs_s[(2 * pair) * 16 + g]     + rs_s[(2 * pair + 1) * 16 + g]);
        float inv_hi = 1.f / (rs_s[(2 * pair) * 16 + g + 8] + rs_s[(2 * pair + 1) * 16 + g + 8]);
        #pragma unroll
        for (int nt = 0; nt < 4; nt++) {
            int c0 = nt * 8 + 2 * tg;
            ag_s[(q0 + g) * 36 + c0]         = (acc[nt][0] + xch[g * XSTR + c0])           * inv_lo;
            ag_s[(q0 + g) * 36 + c0 + 1]     = (acc[nt][1] + xch[g * XSTR + c0 + 1])       * inv_lo;
            ag_s[(q0 + g + 8) * 36 + c0]     = (acc[nt][2] + xch[(g + 8) * XSTR + c0])     * inv_hi;
            ag_s[(q0 + g + 8) * 36 + c0 + 1] = (acc[nt][3] + xch[(g + 8) * XSTR + c0 + 1]) * inv_hi;
        }
    }
    __syncthreads();

    // ---- projection + residual epilogue ----
    float sig = sigma[0];
    int nl = tid & 127;
    int kh = tid >> 7;

    float ag[32];
    #pragma unroll
    for (int c4 = 0; c4 < 8; c4++) {
        float4 v = *(const float4*)(ag_s + nl * 36 + 4 * c4);
        ag[4 * c4 + 0] = v.x; ag[4 * c4 + 1] = v.y;
        ag[4 * c4 + 2] = v.z; ag[4 * c4 + 3] = v.w;
    }
    size_t xoff_base = ((size_t)b * C_ + kh * 16) * N_ + qbase + nl;
    #pragma unroll 4
    for (int kk = 0; kk < 16; kk++) {
        int k = kh * 16 + kk;
        float val = bo_s[k];
        const float4* wrow = (const float4*)(wo_s + k * 32);
        #pragma unroll
        for (int c4 = 0; c4 < 8; c4++) {
            float4 w4 = wrow[c4];
            val += w4.x * ag[4 * c4] + w4.y * ag[4 * c4 + 1]
                 + w4.z * ag[4 * c4 + 2] + w4.w * ag[4 * c4 + 3];
        }
        size_t off = xoff_base + (size_t)kk * N_;
        out[off] = x[off] + sig * val;
    }
}

// ---------------------------------------------------------------------------
extern "C" void kernel_launch(void* const* d_in, const int* in_sizes, int n_in,
                              void* d_out, int out_size)
{
    const float* x       = (const float*)d_in[0];
    const float* w_theta = (const float*)d_in[1];
    const float* b_theta = (const float*)d_in[2];
    const float* w_phi   = (const float*)d_in[3];
    const float* b_phi   = (const float*)d_in[4];
    const float* w_g     = (const float*)d_in[5];
    const float* b_g     = (const float*)d_in[6];
    const float* w_o     = (const float*)d_in[7];
    const float* b_o     = (const float*)d_in[8];
    const float* sigma   = (const float*)d_in[9];
    float* out = (float*)d_out;

    convpool_kernel<<<dim3(B_ * 1024 / 256, 2), 256>>>(x, w_theta, b_theta,
                                                       w_phi, b_phi, w_g, b_g);

    cudaFuncSetAttribute(attn_main_kernel,
                         cudaFuncAttributeMaxDynamicSharedMemorySize, SMEM_REQ);
    attn_main_kernel<<<dim3(N_ / 128, B_), 512, SMEM_REQ>>>(x, w_o, b_o, sigma, out);
}